// round 1
// baseline (speedup 1.0000x reference)
#include <cuda_runtime.h>
#include <cuda_bf16.h>

// CRF dense pairwise loss, B=1, C=2, H=W=96 (fixed by setup_inputs).
// loss = (1/N) * sum_{i,j} K_ij * (1 - S_i . S_j),  K_ij = exp(-dxy/(2*15^2) - drgb/(2*0.125^2))
// Rewritten: K_ij = 2^( g_i.g_j - h_i - h_j ), g = 5-dim scaled feature, h = |g|^2/2.
// Weight (C=2, softmax): w_ij = p_j + p_i*(1-2*p_j).

#define Hdim 96
#define Wdim 96
#define NPIX 9216          // H*W
#define TPB  256
#define IPT  4             // i's per thread
#define ITILE (TPB*IPT)    // 1024
#define NITILES 9          // 9216/1024
#define NJCH 16
#define JCH  (NPIX/NJCH)   // 576
#define NBLK (NITILES*NJCH) // 144

__device__ float g_gy[NPIX];
__device__ float g_gx[NPIX];
__device__ float g_gr[NPIX];
__device__ float g_gg[NPIX];
__device__ float g_gb[NPIX];
__device__ float g_nh[NPIX];   // -h
__device__ float g_p [NPIX];
__device__ float g_q [NPIX];   // 1 - 2p
__device__ float g_part[NBLK];

__global__ void crf_pre(const float* __restrict__ probs,
                        const float* __restrict__ image) {
    int n = blockIdx.x * blockDim.x + threadIdx.x;
    if (n >= NPIX) return;
    // sqrt(2 * log2(e) * inv2sigma): xy: log2e/225 ; rgb: 64*log2e
    const float SXY  = sqrtf(1.4426950408889634f / 225.0f);
    const float SRGB = sqrtf(64.0f * 1.4426950408889634f);
    float y = (float)(n / Wdim);
    float x = (float)(n % Wdim);
    float r = image[n];
    float g = image[NPIX + n];
    float b = image[2 * NPIX + n];
    float gy = y * SXY,  gx = x * SXY;
    float gr = r * SRGB, gg = g * SRGB, gb = b * SRGB;
    float h = 0.5f * (gy*gy + gx*gx + gr*gr + gg*gg + gb*gb);
    float p = probs[n];              // class-0 prob; class-1 = 1-p (softmax)
    g_gy[n] = gy; g_gx[n] = gx;
    g_gr[n] = gr; g_gg[n] = gg; g_gb[n] = gb;
    g_nh[n] = -h;
    g_p [n] = p;
    g_q [n] = 1.0f - 2.0f * p;
}

__global__ void __launch_bounds__(TPB) crf_main() {
    int bid = blockIdx.x;
    int itile = bid / NJCH;
    int jch   = bid % NJCH;
    int ibase = itile * ITILE + threadIdx.x;

    float gy[IPT], gx[IPT], gr[IPT], gg[IPT], gb[IPT], nh[IPT], pi[IPT], acc[IPT];
#pragma unroll
    for (int m = 0; m < IPT; ++m) {
        int i = ibase + m * TPB;
        gy[m] = g_gy[i]; gx[m] = g_gx[i];
        gr[m] = g_gr[i]; gg[m] = g_gg[i]; gb[m] = g_gb[i];
        nh[m] = g_nh[i]; pi[m] = g_p[i];
        acc[m] = 0.0f;
    }

    int j0 = jch * JCH;
#pragma unroll 2
    for (int j = j0; j < j0 + JCH; ++j) {
        // warp-uniform loads (all lanes share j)
        float gyj = __ldg(&g_gy[j]);
        float gxj = __ldg(&g_gx[j]);
        float grj = __ldg(&g_gr[j]);
        float ggj = __ldg(&g_gg[j]);
        float gbj = __ldg(&g_gb[j]);
        float nhj = __ldg(&g_nh[j]);
        float pj  = __ldg(&g_p [j]);
        float qj  = __ldg(&g_q [j]);
#pragma unroll
        for (int m = 0; m < IPT; ++m) {
            float t = nh[m] + nhj;
            t = fmaf(gy[m], gyj, t);
            t = fmaf(gx[m], gxj, t);
            t = fmaf(gr[m], grj, t);
            t = fmaf(gg[m], ggj, t);
            t = fmaf(gb[m], gbj, t);
            float k;
            asm("ex2.approx.ftz.f32 %0, %1;" : "=f"(k) : "f"(t));
            float w = fmaf(pi[m], qj, pj);        // 1 - S_i.S_j  (C=2)
            acc[m] = fmaf(k, w, acc[m]);
        }
    }

    float s = (acc[0] + acc[1]) + (acc[2] + acc[3]);
#pragma unroll
    for (int off = 16; off > 0; off >>= 1)
        s += __shfl_down_sync(0xffffffffu, s, off);

    __shared__ float ws[TPB / 32];
    if ((threadIdx.x & 31) == 0) ws[threadIdx.x >> 5] = s;
    __syncthreads();
    if (threadIdx.x == 0) {
        float t = 0.0f;
#pragma unroll
        for (int k = 0; k < TPB / 32; ++k) t += ws[k];
        g_part[bid] = t;
    }
}

__global__ void crf_finish(float* __restrict__ out) {
    if (threadIdx.x == 0) {
        float a = 0.0f;
        for (int k = 0; k < NBLK; ++k) a += g_part[k];
        out[0] = a * (1.0f / (float)NPIX);   // /N, mean over B=1
    }
}

extern "C" void kernel_launch(void* const* d_in, const int* in_sizes, int n_in,
                              void* d_out, int out_size) {
    const float* probs = (const float*)d_in[0];
    const float* image = (const float*)d_in[1];
    float* out = (float*)d_out;

    crf_pre <<<(NPIX + TPB - 1) / TPB, TPB>>>(probs, image);
    crf_main<<<NBLK, TPB>>>();
    crf_finish<<<1, 32>>>(out);
}

// round 2
// speedup vs baseline: 2.5941x; 2.5941x over previous
#include <cuda_runtime.h>

// Dense CRF pairwise loss, B=1, C=2, H=W=96.
// K_ij = 2^(g_i.g_j - h_i - h_j), g = 5-dim scaled feature, h = |g|^2/2.
// Full sum = sum_{tile a<b} sum_{i in a, j in b} K_ij * 2*(p_i+p_j-2 p_i p_j)
//          + sum_{tile a}   sum_{i,j in a}       K_ij * (p_i+p_j-2 p_i p_j)
// Both weights are fma(p_j, B_i, A_i) with per-i constants (scaled x2 off-diag).

#define Hdim   96
#define Wdim   96
#define NPIX   9216
#define TPB    256
#define IPT    4
#define ITILE  1024          // TPB*IPT
#define NTILES 9             // 9216/1024
#define NTPAIR 45            // triangle incl diagonal
#define NCHUNK 3
#define NBLK   (NTPAIR*NCHUNK)  // 135 blocks = 1 wave on 148 SMs
#define JP_TILE (ITILE/2)    // 512 j-pairs per tile
#define JPMAX  171           // max j-pairs per chunk (ceil(512/3))

__device__ float g_part[NBLK];
__device__ int   g_cnt = 0;

typedef unsigned long long u64;

__device__ __forceinline__ u64 splat2(float v) {
    u64 r; asm("mov.b64 %0,{%1,%1};" : "=l"(r) : "f"(v)); return r;
}
__device__ __forceinline__ u64 pk2(float a, float b) {
    u64 r; asm("mov.b64 %0,{%1,%2};" : "=l"(r) : "f"(a), "f"(b)); return r;
}
__device__ __forceinline__ void up2(u64 v, float& a, float& b) {
    asm("mov.b64 {%0,%1},%2;" : "=f"(a), "=f"(b) : "l"(v));
}
__device__ __forceinline__ u64 fma2(u64 a, u64 b, u64 c) {
    u64 d; asm("fma.rn.f32x2 %0,%1,%2,%3;" : "=l"(d) : "l"(a), "l"(b), "l"(c)); return d;
}
__device__ __forceinline__ u64 add2(u64 a, u64 b) {
    u64 d; asm("add.rn.f32x2 %0,%1,%2;" : "=l"(d) : "l"(a), "l"(b)); return d;
}
__device__ __forceinline__ float ex2f(float x) {
    float r; asm("ex2.approx.ftz.f32 %0,%1;" : "=f"(r) : "f"(x)); return r;
}

// per-pixel feature: gy,gx scaled coords; gr,gg,gb scaled rgb; nh = -|g|^2/2; p = class-0 prob
__device__ __forceinline__ void pix_feat(const float* __restrict__ probs,
                                         const float* __restrict__ image, int n,
                                         float& gy, float& gx, float& gr, float& gg,
                                         float& gb, float& nh, float& p) {
    const float SXY  = 0.080074306f;   // sqrt(log2e/225)
    const float SRGB = 9.6083684f;     // sqrt(64*log2e)
    gy = (float)(n / Wdim) * SXY;
    gx = (float)(n % Wdim) * SXY;
    gr = image[n] * SRGB;
    gg = image[NPIX + n] * SRGB;
    gb = image[2 * NPIX + n] * SRGB;
    nh = -0.5f * (gy*gy + gx*gx + gr*gr + gg*gg + gb*gb);
    p  = probs[n];
}

__global__ void __launch_bounds__(TPB) crf_fused(const float* __restrict__ probs,
                                                 const float* __restrict__ image,
                                                 float* __restrict__ out) {
    __shared__ float4 sA[JPMAX];   // gy0,gy1,gx0,gx1
    __shared__ float4 sB[JPMAX];   // gr0,gr1,gg0,gg1
    __shared__ float4 sC[JPMAX];   // gb0,gb1,nh0,nh1
    __shared__ float2 sP[JPMAX];   // p0,p1
    __shared__ float  ws[TPB / 32];
    __shared__ bool   isLast;

    const int tid = threadIdx.x;
    const int bid = blockIdx.x;
    const int pairIdx = bid / NCHUNK;
    const int chunk   = bid % NCHUNK;

    // tile pair (a <= b) from triangular index
    int a = 0, b = 0, idx = pairIdx;
    #pragma unroll
    for (int aa = 0; aa < NTILES; ++aa) {
        int cnt = NTILES - aa;
        if (idx < cnt) { a = aa; b = aa + idx; break; }
        idx -= cnt;
    }

    const int jp0 = b * JP_TILE + (chunk * JP_TILE) / NCHUNK;
    const int jp1 = b * JP_TILE + ((chunk + 1) * JP_TILE) / NCHUNK;
    const int nJp = jp1 - jp0;

    // stage j-features into smem, packed by j-pair
    if (tid < nJp) {
        int j0 = 2 * (jp0 + tid);
        float gy0, gx0, gr0, gg0, gb0, nh0, p0;
        float gy1, gx1, gr1, gg1, gb1, nh1, p1;
        pix_feat(probs, image, j0,     gy0, gx0, gr0, gg0, gb0, nh0, p0);
        pix_feat(probs, image, j0 + 1, gy1, gx1, gr1, gg1, gb1, nh1, p1);
        sA[tid] = make_float4(gy0, gy1, gx0, gx1);
        sB[tid] = make_float4(gr0, gr1, gg0, gg1);
        sC[tid] = make_float4(gb0, gb1, nh0, nh1);
        sP[tid] = make_float2(p0, p1);
    }

    // i-features: IPT rows per thread, splat-packed
    const float wscale = (a == b) ? 1.0f : 2.0f;
    u64 gyi[IPT], gxi[IPT], gri[IPT], ggi[IPT], gbi[IPT], nhi[IPT], Ai[IPT], Bi[IPT], acc[IPT];
    #pragma unroll
    for (int m = 0; m < IPT; ++m) {
        int i = a * ITILE + tid + m * TPB;
        float gy, gx, gr, gg, gb, nh, p;
        pix_feat(probs, image, i, gy, gx, gr, gg, gb, nh, p);
        gyi[m] = splat2(gy); gxi[m] = splat2(gx);
        gri[m] = splat2(gr); ggi[m] = splat2(gg); gbi[m] = splat2(gb);
        nhi[m] = splat2(nh);
        Ai[m] = splat2(wscale * p);
        Bi[m] = splat2(wscale * (1.0f - 2.0f * p));
        acc[m] = 0ull;
    }
    __syncthreads();

    #pragma unroll 2
    for (int jp = 0; jp < nJp; ++jp) {
        float4 A = sA[jp], B = sB[jp], C = sC[jp];
        float2 P = sP[jp];
        u64 gyj = pk2(A.x, A.y), gxj = pk2(A.z, A.w);
        u64 grj = pk2(B.x, B.y), ggj = pk2(B.z, B.w);
        u64 gbj = pk2(C.x, C.y), nhj = pk2(C.z, C.w);
        u64 pj  = pk2(P.x, P.y);
        #pragma unroll
        for (int m = 0; m < IPT; ++m) {
            u64 t = add2(nhi[m], nhj);
            t = fma2(gyi[m], gyj, t);
            t = fma2(gxi[m], gxj, t);
            t = fma2(gri[m], grj, t);
            t = fma2(ggi[m], ggj, t);
            t = fma2(gbi[m], gbj, t);
            float t0, t1; up2(t, t0, t1);
            float k0 = ex2f(t0);
            float k1 = ex2f(t1);
            u64 w = fma2(pj, Bi[m], Ai[m]);
            acc[m] = fma2(pk2(k0, k1), w, acc[m]);
        }
    }

    // block reduction (fixed order -> deterministic)
    float s = 0.0f;
    #pragma unroll
    for (int m = 0; m < IPT; ++m) {
        float lo, hi; up2(acc[m], lo, hi);
        s += lo + hi;
    }
    #pragma unroll
    for (int off = 16; off > 0; off >>= 1)
        s += __shfl_down_sync(0xffffffffu, s, off);
    if ((tid & 31) == 0) ws[tid >> 5] = s;
    __syncthreads();
    if (tid == 0) {
        float t = 0.0f;
        #pragma unroll
        for (int k = 0; k < TPB / 32; ++k) t += ws[k];
        g_part[bid] = t;
        __threadfence();
        int old = atomicAdd(&g_cnt, 1);
        isLast = (old == NBLK - 1);
    }
    __syncthreads();
    if (isLast && tid == 0) {
        __threadfence();
        float acc2 = 0.0f;
        for (int k = 0; k < NBLK; ++k) acc2 += __ldcg(&g_part[k]);
        out[0] = acc2 * (1.0f / (float)NPIX);
        g_cnt = 0;   // reset for next replay
    }
}

extern "C" void kernel_launch(void* const* d_in, const int* in_sizes, int n_in,
                              void* d_out, int out_size) {
    const float* probs = (const float*)d_in[0];
    const float* image = (const float*)d_in[1];
    float* out = (float*)d_out;
    crf_fused<<<NBLK, TPB>>>(probs, image, out);
}

// round 3
// speedup vs baseline: 3.0408x; 1.1722x over previous
#include <cuda_runtime.h>

// Dense CRF pairwise loss, B=1, C=2, H=W=96.
// K_ij = 2^(g_i.g_j - h_i - h_j), g = 5-dim scaled feature, h = |g|^2/2.
// Symmetry: full sum = sum_{a<=b tile pairs} w-scaled partial sums, with
// per-pair weight A_i + B_i*p_j hoisted: Sum k*(A+B*pj) = A*Sum(k) + B*Sum(k*pj).

#define Hdim   96
#define Wdim   96
#define NPIX   9216
#define TPB    512
#define IPT    2
#define ITILE  1024          // TPB*IPT
#define NTILES 9             // 9216/1024
#define NTPAIR 45            // triangle incl diagonal
#define NCHUNK 3
#define NBLK   (NTPAIR*NCHUNK)  // 135 blocks = 1 wave
#define JP_TILE (ITILE/2)    // 512 j-pairs per tile
#define JPMAX  171           // ceil(512/3)

__device__ float g_part[NBLK];
__device__ int   g_cnt = 0;

typedef unsigned long long u64;

__device__ __forceinline__ u64 splat2(float v) {
    u64 r; asm("mov.b64 %0,{%1,%1};" : "=l"(r) : "f"(v)); return r;
}
__device__ __forceinline__ u64 pk2(float a, float b) {
    u64 r; asm("mov.b64 %0,{%1,%2};" : "=l"(r) : "f"(a), "f"(b)); return r;
}
__device__ __forceinline__ void up2(u64 v, float& a, float& b) {
    asm("mov.b64 {%0,%1},%2;" : "=f"(a), "=f"(b) : "l"(v));
}
__device__ __forceinline__ u64 fma2(u64 a, u64 b, u64 c) {
    u64 d; asm("fma.rn.f32x2 %0,%1,%2,%3;" : "=l"(d) : "l"(a), "l"(b), "l"(c)); return d;
}
__device__ __forceinline__ u64 add2(u64 a, u64 b) {
    u64 d; asm("add.rn.f32x2 %0,%1,%2;" : "=l"(d) : "l"(a), "l"(b)); return d;
}
__device__ __forceinline__ float ex2f(float x) {
    float r; asm("ex2.approx.ftz.f32 %0,%1;" : "=f"(r) : "f"(x)); return r;
}

__device__ __forceinline__ void pix_feat(const float* __restrict__ probs,
                                         const float* __restrict__ image, int n,
                                         float& gy, float& gx, float& gr, float& gg,
                                         float& gb, float& nh, float& p) {
    const float SXY  = 0.080074306f;   // sqrt(log2e/225)
    const float SRGB = 9.6083684f;     // sqrt(64*log2e)
    gy = (float)(n / Wdim) * SXY;
    gx = (float)(n % Wdim) * SXY;
    gr = image[n] * SRGB;
    gg = image[NPIX + n] * SRGB;
    gb = image[2 * NPIX + n] * SRGB;
    nh = -0.5f * (gy*gy + gx*gx + gr*gr + gg*gg + gb*gb);
    p  = probs[n];
}

__global__ void __launch_bounds__(TPB) crf_fused(const float* __restrict__ probs,
                                                 const float* __restrict__ image,
                                                 float* __restrict__ out) {
    // j-features packed as u64 f32x2 pairs: LDS.128 reg pairs feed fma.f32x2 directly
    __shared__ ulonglong2 sA[JPMAX];   // {gy01, gx01}
    __shared__ ulonglong2 sB[JPMAX];   // {gr01, gg01}
    __shared__ ulonglong2 sC[JPMAX];   // {gb01, nh01}
    __shared__ u64        sP[JPMAX];   // p01
    __shared__ float      ws[TPB / 32];
    __shared__ bool       isLast;

    const int tid = threadIdx.x;
    const int bid = blockIdx.x;
    const int pairIdx = bid / NCHUNK;
    const int chunk   = bid % NCHUNK;

    int a = 0, b = 0, idx = pairIdx;
    #pragma unroll
    for (int aa = 0; aa < NTILES; ++aa) {
        int cnt = NTILES - aa;
        if (idx < cnt) { a = aa; b = aa + idx; break; }
        idx -= cnt;
    }

    const int jp0 = b * JP_TILE + (chunk * JP_TILE) / NCHUNK;
    const int jp1 = b * JP_TILE + ((chunk + 1) * JP_TILE) / NCHUNK;
    const int nJp = jp1 - jp0;

    if (tid < nJp) {
        int j0 = 2 * (jp0 + tid);
        float gy0, gx0, gr0, gg0, gb0, nh0, p0;
        float gy1, gx1, gr1, gg1, gb1, nh1, p1;
        pix_feat(probs, image, j0,     gy0, gx0, gr0, gg0, gb0, nh0, p0);
        pix_feat(probs, image, j0 + 1, gy1, gx1, gr1, gg1, gb1, nh1, p1);
        sA[tid] = make_ulonglong2(pk2(gy0, gy1), pk2(gx0, gx1));
        sB[tid] = make_ulonglong2(pk2(gr0, gr1), pk2(gg0, gg1));
        sC[tid] = make_ulonglong2(pk2(gb0, gb1), pk2(nh0, nh1));
        sP[tid] = pk2(p0, p1);
    }

    const float wscale = (a == b) ? 1.0f : 2.0f;
    u64 gyi[IPT], gxi[IPT], gri[IPT], ggi[IPT], gbi[IPT], nhi[IPT];
    u64 accA[IPT], accB[IPT];          // Sum k ; Sum k*pj
    float Ai[IPT], Bi[IPT];
    #pragma unroll
    for (int m = 0; m < IPT; ++m) {
        int i = a * ITILE + tid + m * TPB;
        float gy, gx, gr, gg, gb, nh, p;
        pix_feat(probs, image, i, gy, gx, gr, gg, gb, nh, p);
        gyi[m] = splat2(gy); gxi[m] = splat2(gx);
        gri[m] = splat2(gr); ggi[m] = splat2(gg); gbi[m] = splat2(gb);
        nhi[m] = splat2(nh);
        Ai[m] = wscale * p;
        Bi[m] = wscale * (1.0f - 2.0f * p);
        accA[m] = 0ull; accB[m] = 0ull;
    }
    __syncthreads();

    #pragma unroll 2
    for (int jp = 0; jp < nJp; ++jp) {
        ulonglong2 A = sA[jp], B = sB[jp], C = sC[jp];
        u64 pj = sP[jp];
        #pragma unroll
        for (int m = 0; m < IPT; ++m) {
            u64 t = add2(nhi[m], C.y);
            t = fma2(gyi[m], A.x, t);
            t = fma2(gxi[m], A.y, t);
            t = fma2(gri[m], B.x, t);
            t = fma2(ggi[m], B.y, t);
            t = fma2(gbi[m], C.x, t);
            float t0, t1; up2(t, t0, t1);
            u64 k = pk2(ex2f(t0), ex2f(t1));
            accA[m] = add2(accA[m], k);
            accB[m] = fma2(k, pj, accB[m]);
        }
    }

    // apply per-i weights, reduce (fixed order -> deterministic)
    float s = 0.0f;
    #pragma unroll
    for (int m = 0; m < IPT; ++m) {
        float a0, a1, b0, b1;
        up2(accA[m], a0, a1);
        up2(accB[m], b0, b1);
        s += Ai[m] * (a0 + a1) + Bi[m] * (b0 + b1);
    }
    #pragma unroll
    for (int off = 16; off > 0; off >>= 1)
        s += __shfl_down_sync(0xffffffffu, s, off);
    if ((tid & 31) == 0) ws[tid >> 5] = s;
    __syncthreads();
    if (tid == 0) {
        float t = 0.0f;
        #pragma unroll
        for (int k = 0; k < TPB / 32; ++k) t += ws[k];
        g_part[bid] = t;
        __threadfence();
        int old = atomicAdd(&g_cnt, 1);
        isLast = (old == NBLK - 1);
    }
    __syncthreads();
    if (isLast && tid == 0) {
        __threadfence();
        float acc2 = 0.0f;
        for (int k = 0; k < NBLK; ++k) acc2 += __ldcg(&g_part[k]);
        out[0] = acc2 * (1.0f / (float)NPIX);
        g_cnt = 0;   // reset for next graph replay
    }
}

extern "C" void kernel_launch(void* const* d_in, const int* in_sizes, int n_in,
                              void* d_out, int out_size) {
    const float* probs = (const float*)d_in[0];
    const float* image = (const float*)d_in[1];
    float* out = (float*)d_out;
    crf_fused<<<NBLK, TPB>>>(probs, image, out);
}